// round 15
// baseline (speedup 1.0000x reference)
#include <cuda_runtime.h>
#include <cuda_bf16.h>
#include <math_constants.h>

// Fused greedy CTC decode — FINAL (best measured: 25.056us total).
//   index[t] = argmax_v emission[t, v]  (first occurrence on ties)
//   char[t]  = -1 if index==0 ; index-1 if index>1 ; 0 if index==1
//   keep[t]  = (char[t] != char[t-1]) && (char[t] != -1)   (char[-1] := -2)
// Output (float32): [0..T) = (float)index, [T..2T) = keep (0.0/1.0).
//
// Session conclusion (11 variants): the streaming-argmax pattern is bound
// by a path-independent effective BW ceiling of ~5.7 TB/s (~72% of spec);
// LDG and cp.async.bulk are equivalent, and occupancy 36-91%, reduce
// style, ILP, wave count, and cache hints all land within noise.
// Config: 8 warps x 4 rows = 32 rows/block, grid 2048. Argmax = batched
// float4 loads -> shallow fmaxf tree -> REDUX max on monotone key ->
// equality-selects + min tree -> REDUX min (first-occurrence semantics).
// Last warp redundantly argmaxes the block's predecessor row (+3.1% HBM,
// cheaper than a second kernel's ~4us launch floor or any cross-block
// dependency chain).

static constexpr int V = 512;
static constexpr int WARPS = 8;
static constexpr int R = 4;                         // rows per warp
static constexpr int ROWS_PER_BLOCK = WARPS * R;    // 32

// Strictly monotone float -> uint map (order- and equality-preserving).
__device__ __forceinline__ unsigned mono(float f)
{
    unsigned u = __float_as_uint(f);
    return u ^ ((unsigned)((int)u >> 31) | 0x80000000u);
}

// Inverse of mono().
__device__ __forceinline__ float inv_mono(unsigned k)
{
    unsigned u = k ^ ((~(unsigned)((int)k >> 31)) | 0x80000000u);
    return __uint_as_float(u);
}

// Warp argmax of one row; returns first-occurrence argmax (uniform).
__device__ __forceinline__ int warp_argmax_row(const float* __restrict__ em,
                                               int row, int lane)
{
    const float4* __restrict__ p =
        reinterpret_cast<const float4*>(em + (size_t)row * V);

    // Lane covers elements {lane*4 + c*128 + k}, c=0..3, k=0..3.
    float4 v0 = p[lane];
    float4 v1 = p[lane + 32];
    float4 v2 = p[lane + 64];
    float4 v3 = p[lane + 96];

    // Shallow max tree over the 16 lane-local values (FMA pipe).
    float m01 = fmaxf(fmaxf(v0.x, v0.y), fmaxf(v0.z, v0.w));
    float m23 = fmaxf(fmaxf(v1.x, v1.y), fmaxf(v1.z, v1.w));
    float m45 = fmaxf(fmaxf(v2.x, v2.y), fmaxf(v2.z, v2.w));
    float m67 = fmaxf(fmaxf(v3.x, v3.y), fmaxf(v3.z, v3.w));
    float lmax = fmaxf(fmaxf(m01, m23), fmaxf(m45, m67));

    // Warp max in one REDUX.
    const unsigned wkey = __reduce_max_sync(0xFFFFFFFFu, mono(lmax));
    const float wm = inv_mono(wkey);

    // First-occurrence index: independent equality-selects, then min tree.
    const int e0 = lane * 4, e1 = e0 + 128, e2 = e0 + 256, e3 = e0 + 384;
    const int BIG = 0x7FFFFFFF;
    int c0  = (v0.x == wm) ? e0     : BIG;
    int c1  = (v0.y == wm) ? e0 + 1 : BIG;
    int c2  = (v0.z == wm) ? e0 + 2 : BIG;
    int c3  = (v0.w == wm) ? e0 + 3 : BIG;
    int c4  = (v1.x == wm) ? e1     : BIG;
    int c5  = (v1.y == wm) ? e1 + 1 : BIG;
    int c6  = (v1.z == wm) ? e1 + 2 : BIG;
    int c7  = (v1.w == wm) ? e1 + 3 : BIG;
    int c8  = (v2.x == wm) ? e2     : BIG;
    int c9  = (v2.y == wm) ? e2 + 1 : BIG;
    int c10 = (v2.z == wm) ? e2 + 2 : BIG;
    int c11 = (v2.w == wm) ? e2 + 3 : BIG;
    int c12 = (v3.x == wm) ? e3     : BIG;
    int c13 = (v3.y == wm) ? e3 + 1 : BIG;
    int c14 = (v3.z == wm) ? e3 + 2 : BIG;
    int c15 = (v3.w == wm) ? e3 + 3 : BIG;

    int a = min(min(min(c0, c1), min(c2, c3)), min(min(c4, c5), min(c6, c7)));
    int b = min(min(min(c8, c9), min(c10, c11)),
                min(min(c12, c13), min(c14, c15)));
    const int cand = min(a, b);

    return (int)__reduce_min_sync(0xFFFFFFFFu, (unsigned)cand);
}

__device__ __forceinline__ int ctc_char(int i)
{
    return (i == 0) ? -1 : ((i > 1) ? i - 1 : 0);
}

__global__ __launch_bounds__(WARPS * 32)
void ctc_fused_kernel(const float* __restrict__ em,
                      float* __restrict__ out_index,
                      float* __restrict__ out_keep,
                      int T)
{
    __shared__ int ch[ROWS_PER_BLOCK + 1];   // ch[0] = char of row base-1

    const int warp = threadIdx.x >> 5;
    const int lane = threadIdx.x & 31;
    const int base = blockIdx.x * ROWS_PER_BLOCK;

#pragma unroll
    for (int j = 0; j < R; ++j) {
        const int local = warp * R + j;
        const int row   = base + local;
        const int bidx  = warp_argmax_row(em, row, lane);
        if (lane == 0) {
            out_index[row] = (float)bidx;
            ch[1 + local]  = ctc_char(bidx);
        }
    }

    // Last warp resolves the block-boundary predecessor row.
    if (warp == WARPS - 1) {
        if (base == 0) {
            if (lane == 0) ch[0] = -2;           // char[-1] sentinel
        } else {
            const int bi = warp_argmax_row(em, base - 1, lane);
            if (lane == 0) ch[0] = ctc_char(bi);
        }
    }
    __syncthreads();

    if (threadIdx.x < ROWS_PER_BLOCK) {
        const int t = base + threadIdx.x;
        const int c  = ch[threadIdx.x + 1];
        const int pc = ch[threadIdx.x];
        out_keep[t] = (c != pc && c != -1) ? 1.0f : 0.0f;
    }
}

extern "C" void kernel_launch(void* const* d_in, const int* in_sizes, int n_in,
                              void* d_out, int out_size)
{
    const float* em = (const float*)d_in[0];
    const int T = in_sizes[0] / V;           // 65536 (divisible by 32)

    float* out       = (float*)d_out;
    float* out_index = out;
    float* out_keep  = out + T;

    const int grid = T / ROWS_PER_BLOCK;     // 2048
    ctc_fused_kernel<<<grid, WARPS * 32>>>(em, out_index, out_keep, T);
}

// round 16
// speedup vs baseline: 1.0191x; 1.0191x over previous
#include <cuda_runtime.h>
#include <cuda_bf16.h>
#include <math_constants.h>

// Fused greedy CTC decode — balanced-boundary variant.
//   index[t] = argmax_v emission[t, v]  (first occurrence on ties)
//   char[t]  = -1 if index==0 ; index-1 if index>1 ; 0 if index==1
//   keep[t]  = (char[t] != char[t-1]) && (char[t] != -1)   (char[-1] := -2)
// Output (float32): [0..T) = (float)index, [T..2T) = keep (0.0/1.0).
//
// 8 warps x 4 rows = 32 rows/block, grid 2048. fmaxf-tree + REDUX argmax.
// The block-boundary predecessor row is SPLIT across all 8 warps (64
// elements each, one float2/lane) so every warp does a uniform 4.125
// rows — no straggler warp at the __syncthreads. Partials (key,idx) are
// combined inline by the epilogue thread that owns t == base.

static constexpr int V = 512;
static constexpr int WARPS = 8;
static constexpr int R = 4;                         // rows per warp
static constexpr int ROWS_PER_BLOCK = WARPS * R;    // 32

// Strictly monotone float -> uint map (order- and equality-preserving).
__device__ __forceinline__ unsigned mono(float f)
{
    unsigned u = __float_as_uint(f);
    return u ^ ((unsigned)((int)u >> 31) | 0x80000000u);
}

// Inverse of mono().
__device__ __forceinline__ float inv_mono(unsigned k)
{
    unsigned u = k ^ ((~(unsigned)((int)k >> 31)) | 0x80000000u);
    return __uint_as_float(u);
}

// Warp argmax of one full row; returns first-occurrence argmax (uniform).
__device__ __forceinline__ int warp_argmax_row(const float* __restrict__ em,
                                               int row, int lane)
{
    const float4* __restrict__ p =
        reinterpret_cast<const float4*>(em + (size_t)row * V);

    float4 v0 = p[lane];
    float4 v1 = p[lane + 32];
    float4 v2 = p[lane + 64];
    float4 v3 = p[lane + 96];

    // Shallow max tree over the 16 lane-local values (FMA pipe).
    float m01 = fmaxf(fmaxf(v0.x, v0.y), fmaxf(v0.z, v0.w));
    float m23 = fmaxf(fmaxf(v1.x, v1.y), fmaxf(v1.z, v1.w));
    float m45 = fmaxf(fmaxf(v2.x, v2.y), fmaxf(v2.z, v2.w));
    float m67 = fmaxf(fmaxf(v3.x, v3.y), fmaxf(v3.z, v3.w));
    float lmax = fmaxf(fmaxf(m01, m23), fmaxf(m45, m67));

    const unsigned wkey = __reduce_max_sync(0xFFFFFFFFu, mono(lmax));
    const float wm = inv_mono(wkey);

    // First-occurrence index: independent equality-selects, then min tree.
    const int e0 = lane * 4, e1 = e0 + 128, e2 = e0 + 256, e3 = e0 + 384;
    const int BIG = 0x7FFFFFFF;
    int c0  = (v0.x == wm) ? e0     : BIG;
    int c1  = (v0.y == wm) ? e0 + 1 : BIG;
    int c2  = (v0.z == wm) ? e0 + 2 : BIG;
    int c3  = (v0.w == wm) ? e0 + 3 : BIG;
    int c4  = (v1.x == wm) ? e1     : BIG;
    int c5  = (v1.y == wm) ? e1 + 1 : BIG;
    int c6  = (v1.z == wm) ? e1 + 2 : BIG;
    int c7  = (v1.w == wm) ? e1 + 3 : BIG;
    int c8  = (v2.x == wm) ? e2     : BIG;
    int c9  = (v2.y == wm) ? e2 + 1 : BIG;
    int c10 = (v2.z == wm) ? e2 + 2 : BIG;
    int c11 = (v2.w == wm) ? e2 + 3 : BIG;
    int c12 = (v3.x == wm) ? e3     : BIG;
    int c13 = (v3.y == wm) ? e3 + 1 : BIG;
    int c14 = (v3.z == wm) ? e3 + 2 : BIG;
    int c15 = (v3.w == wm) ? e3 + 3 : BIG;

    int a = min(min(min(c0, c1), min(c2, c3)), min(min(c4, c5), min(c6, c7)));
    int b = min(min(min(c8, c9), min(c10, c11)),
                min(min(c12, c13), min(c14, c15)));
    const int cand = min(a, b);

    return (int)__reduce_min_sync(0xFFFFFFFFu, (unsigned)cand);
}

__device__ __forceinline__ int ctc_char(int i)
{
    return (i == 0) ? -1 : ((i > 1) ? i - 1 : 0);
}

__global__ __launch_bounds__(WARPS * 32)
void ctc_fused_kernel(const float* __restrict__ em,
                      float* __restrict__ out_index,
                      float* __restrict__ out_keep,
                      int T)
{
    __shared__ int ch[ROWS_PER_BLOCK + 1];   // ch[0] unused if base==0
    __shared__ unsigned pkey[WARPS];         // predecessor-row partials
    __shared__ int      pidx[WARPS];

    const int warp = threadIdx.x >> 5;
    const int lane = threadIdx.x & 31;
    const int base = blockIdx.x * ROWS_PER_BLOCK;

    // Balanced predecessor-row slice FIRST: warp w covers 64 elements
    // [w*64, w*64+64) of row base-1 (one float2 per lane).
    if (base != 0) {
        const float2* __restrict__ q = reinterpret_cast<const float2*>(
            em + (size_t)(base - 1) * V) + warp * 32 + lane;
        const float2 v = *q;
        const int e = warp * 64 + lane * 2;
        float best; int bidx;
        if (v.y > v.x) { best = v.y; bidx = e + 1; }
        else           { best = v.x; bidx = e;     }
        const unsigned k = mono(best);
        const unsigned m = __reduce_max_sync(0xFFFFFFFFu, k);
        const unsigned cand = (k == m) ? (unsigned)bidx : 0x7FFFFFFFu;
        const int wi = (int)__reduce_min_sync(0xFFFFFFFFu, cand);
        if (lane == 0) { pkey[warp] = m; pidx[warp] = wi; }
    }

    // Main work: 4 full rows per warp.
#pragma unroll
    for (int j = 0; j < R; ++j) {
        const int local = warp * R + j;
        const int row   = base + local;
        const int bidx  = warp_argmax_row(em, row, lane);
        if (lane == 0) {
            out_index[row] = (float)bidx;
            ch[1 + local]  = ctc_char(bidx);
        }
    }
    __syncthreads();

    if (threadIdx.x < ROWS_PER_BLOCK) {
        const int t = base + threadIdx.x;
        const int c = ch[threadIdx.x + 1];
        int pc;
        if (threadIdx.x == 0) {
            if (base == 0) {
                pc = -2;                          // char[-1] sentinel
            } else {
                // Combine 8 partials: max key, min index on ties.
                unsigned bk = pkey[0]; int bi = pidx[0];
#pragma unroll
                for (int w = 1; w < WARPS; ++w) {
                    const unsigned k = pkey[w];
                    const int      i = pidx[w];
                    if (k > bk || (k == bk && i < bi)) { bk = k; bi = i; }
                }
                pc = ctc_char(bi);
            }
        } else {
            pc = ch[threadIdx.x];
        }
        out_keep[t] = (c != pc && c != -1) ? 1.0f : 0.0f;
    }
}

extern "C" void kernel_launch(void* const* d_in, const int* in_sizes, int n_in,
                              void* d_out, int out_size)
{
    const float* em = (const float*)d_in[0];
    const int T = in_sizes[0] / V;           // 65536 (divisible by 32)

    float* out       = (float*)d_out;
    float* out_index = out;
    float* out_keep  = out + T;

    const int grid = T / ROWS_PER_BLOCK;     // 2048
    ctc_fused_kernel<<<grid, WARPS * 32>>>(em, out_index, out_keep, T);
}

// round 17
// speedup vs baseline: 1.0204x; 1.0013x over previous
#include <cuda_runtime.h>
#include <cuda_bf16.h>
#include <math_constants.h>

// Fused greedy CTC decode — FINAL.
//   index[t] = argmax_v emission[t, v]  (first occurrence on ties)
//   char[t]  = -1 if index==0 ; index-1 if index>1 ; 0 if index==1
//   keep[t]  = (char[t] != char[t-1]) && (char[t] != -1)   (char[-1] := -2)
// Output (float32): [0..T) = (float)index, [T..2T) = keep (0.0/1.0).
//
// Session conclusion (13 variants): this streaming-argmax pattern is bound
// by a path-independent effective BW ceiling of ~5.7 TB/s (~72% of spec).
// LDG == cp.async.bulk; occupancy 36-91%, reduce style, ILP, wave count,
// cache hints, boundary placement: all within +-0.2us noise at the plateau.
//
// Config: 8 warps x 4 rows = 32 rows/block, grid 2048. Argmax = batched
// float4 loads -> shallow fmaxf tree -> REDUX max on monotone key ->
// equality-selects + min tree -> REDUX min (first-occurrence semantics).
// Block-boundary predecessor row split across all 8 warps (uniform 4.125
// rows/warp, +3.1% HBM — cheaper than a 2nd kernel's ~4us launch floor or
// any cross-block dependency chain). Coalesced keep epilogue.

static constexpr int V = 512;
static constexpr int WARPS = 8;
static constexpr int R = 4;                         // rows per warp
static constexpr int ROWS_PER_BLOCK = WARPS * R;    // 32

// Strictly monotone float -> uint map (order- and equality-preserving).
__device__ __forceinline__ unsigned mono(float f)
{
    unsigned u = __float_as_uint(f);
    return u ^ ((unsigned)((int)u >> 31) | 0x80000000u);
}

// Inverse of mono().
__device__ __forceinline__ float inv_mono(unsigned k)
{
    unsigned u = k ^ ((~(unsigned)((int)k >> 31)) | 0x80000000u);
    return __uint_as_float(u);
}

// Warp argmax of one full row; returns first-occurrence argmax (uniform).
__device__ __forceinline__ int warp_argmax_row(const float* __restrict__ em,
                                               int row, int lane)
{
    const float4* __restrict__ p =
        reinterpret_cast<const float4*>(em + (size_t)row * V);

    float4 v0 = p[lane];
    float4 v1 = p[lane + 32];
    float4 v2 = p[lane + 64];
    float4 v3 = p[lane + 96];

    // Shallow max tree over the 16 lane-local values (FMA pipe).
    float m01 = fmaxf(fmaxf(v0.x, v0.y), fmaxf(v0.z, v0.w));
    float m23 = fmaxf(fmaxf(v1.x, v1.y), fmaxf(v1.z, v1.w));
    float m45 = fmaxf(fmaxf(v2.x, v2.y), fmaxf(v2.z, v2.w));
    float m67 = fmaxf(fmaxf(v3.x, v3.y), fmaxf(v3.z, v3.w));
    float lmax = fmaxf(fmaxf(m01, m23), fmaxf(m45, m67));

    const unsigned wkey = __reduce_max_sync(0xFFFFFFFFu, mono(lmax));
    const float wm = inv_mono(wkey);

    // First-occurrence index: independent equality-selects, then min tree.
    const int e0 = lane * 4, e1 = e0 + 128, e2 = e0 + 256, e3 = e0 + 384;
    const int BIG = 0x7FFFFFFF;
    int c0  = (v0.x == wm) ? e0     : BIG;
    int c1  = (v0.y == wm) ? e0 + 1 : BIG;
    int c2  = (v0.z == wm) ? e0 + 2 : BIG;
    int c3  = (v0.w == wm) ? e0 + 3 : BIG;
    int c4  = (v1.x == wm) ? e1     : BIG;
    int c5  = (v1.y == wm) ? e1 + 1 : BIG;
    int c6  = (v1.z == wm) ? e1 + 2 : BIG;
    int c7  = (v1.w == wm) ? e1 + 3 : BIG;
    int c8  = (v2.x == wm) ? e2     : BIG;
    int c9  = (v2.y == wm) ? e2 + 1 : BIG;
    int c10 = (v2.z == wm) ? e2 + 2 : BIG;
    int c11 = (v2.w == wm) ? e2 + 3 : BIG;
    int c12 = (v3.x == wm) ? e3     : BIG;
    int c13 = (v3.y == wm) ? e3 + 1 : BIG;
    int c14 = (v3.z == wm) ? e3 + 2 : BIG;
    int c15 = (v3.w == wm) ? e3 + 3 : BIG;

    int a = min(min(min(c0, c1), min(c2, c3)), min(min(c4, c5), min(c6, c7)));
    int b = min(min(min(c8, c9), min(c10, c11)),
                min(min(c12, c13), min(c14, c15)));
    const int cand = min(a, b);

    return (int)__reduce_min_sync(0xFFFFFFFFu, (unsigned)cand);
}

__device__ __forceinline__ int ctc_char(int i)
{
    return (i == 0) ? -1 : ((i > 1) ? i - 1 : 0);
}

__global__ __launch_bounds__(WARPS * 32)
void ctc_fused_kernel(const float* __restrict__ em,
                      float* __restrict__ out_index,
                      float* __restrict__ out_keep,
                      int T)
{
    __shared__ int ch[ROWS_PER_BLOCK + 1];   // ch[0] unused if base==0
    __shared__ unsigned pkey[WARPS];         // predecessor-row partials
    __shared__ int      pidx[WARPS];

    const int warp = threadIdx.x >> 5;
    const int lane = threadIdx.x & 31;
    const int base = blockIdx.x * ROWS_PER_BLOCK;

    // Balanced predecessor-row slice FIRST: warp w covers 64 elements
    // [w*64, w*64+64) of row base-1 (one float2 per lane).
    if (base != 0) {
        const float2* __restrict__ q = reinterpret_cast<const float2*>(
            em + (size_t)(base - 1) * V) + warp * 32 + lane;
        const float2 v = *q;
        const int e = warp * 64 + lane * 2;
        float best; int bidx;
        if (v.y > v.x) { best = v.y; bidx = e + 1; }
        else           { best = v.x; bidx = e;     }
        const unsigned k = mono(best);
        const unsigned m = __reduce_max_sync(0xFFFFFFFFu, k);
        const unsigned cand = (k == m) ? (unsigned)bidx : 0x7FFFFFFFu;
        const int wi = (int)__reduce_min_sync(0xFFFFFFFFu, cand);
        if (lane == 0) { pkey[warp] = m; pidx[warp] = wi; }
    }

    // Main work: 4 full rows per warp.
#pragma unroll
    for (int j = 0; j < R; ++j) {
        const int local = warp * R + j;
        const int row   = base + local;
        const int bidx  = warp_argmax_row(em, row, lane);
        if (lane == 0) {
            out_index[row] = (float)bidx;
            ch[1 + local]  = ctc_char(bidx);
        }
    }
    __syncthreads();

    if (threadIdx.x < ROWS_PER_BLOCK) {
        const int t = base + threadIdx.x;
        const int c = ch[threadIdx.x + 1];
        int pc;
        if (threadIdx.x == 0) {
            if (base == 0) {
                pc = -2;                          // char[-1] sentinel
            } else {
                // Combine 8 partials: max key, min index on ties.
                unsigned bk = pkey[0]; int bi = pidx[0];
#pragma unroll
                for (int w = 1; w < WARPS; ++w) {
                    const unsigned k = pkey[w];
                    const int      i = pidx[w];
                    if (k > bk || (k == bk && i < bi)) { bk = k; bi = i; }
                }
                pc = ctc_char(bi);
            }
        } else {
            pc = ch[threadIdx.x];
        }
        out_keep[t] = (c != pc && c != -1) ? 1.0f : 0.0f;
    }
}

extern "C" void kernel_launch(void* const* d_in, const int* in_sizes, int n_in,
                              void* d_out, int out_size)
{
    const float* em = (const float*)d_in[0];
    const int T = in_sizes[0] / V;           // 65536 (divisible by 32)

    float* out       = (float*)d_out;
    float* out_index = out;
    float* out_keep  = out + T;

    const int grid = T / ROWS_PER_BLOCK;     // 2048
    ctc_fused_kernel<<<grid, WARPS * 32>>>(em, out_index, out_keep, T);
}